// round 1
// baseline (speedup 1.0000x reference)
#include <cuda_runtime.h>
#include <cuda_bf16.h>

// Shapes: B=32, S=2048, I=128, A=128, H=256, K=8, ACTIVE=3 (structurally k=0,1,2)
#define NB 32
#define NS 2048
#define NI 128
#define NA 128
#define NH 256
#define NK 8
#define KACT 3
#define CHUNKS 16           // blocks per batch in main kernel
#define ROWS_PER_BLOCK (NS / CHUNKS)   // 128
#define ROWS_PER_WARP (ROWS_PER_BLOCK / 8) // 16

// Device scratch (allocation-free rule: __device__ globals)
__device__ float g_u[KACT][NI];                 // u[k] = W_k[k] @ q[k]
__device__ float g_hpre[KACT][NH];              // rim[k] @ W_hh + b
__device__ float g_ypart[NB][CHUNKS][KACT * NI]; // per-chunk partial y

// ---------------------------------------------------------------------------
// Prologue: blocks 0..2 -> q[k] then u[k];  blocks 3..4 -> hpre halves
// ---------------------------------------------------------------------------
__global__ __launch_bounds__(256) void prologue_kernel(
    const float* __restrict__ rim, const float* __restrict__ Wq,
    const float* __restrict__ Wk, const float* __restrict__ Whh,
    const float* __restrict__ bias)
{
    const int tid = threadIdx.x;
    const int bid = blockIdx.x;

    if (bid < KACT) {
        const int k = bid;
        __shared__ float qp[2][NA];
        __shared__ float qs[NA];
        // q[k][a] = sum_h rim[k][h] * Wq[k][h][a]   (split h over two half-blocks)
        {
            const int a = tid & 127;
            const int hh = tid >> 7;       // 0 or 1
            const float* wq = Wq + ((size_t)(k * NH + hh * 128)) * NA + a;
            const float* rk = rim + k * NH + hh * 128;
            float acc = 0.f;
            #pragma unroll 8
            for (int h = 0; h < 128; ++h) acc += rk[h] * wq[(size_t)h * NA];
            qp[hh][a] = acc;
        }
        __syncthreads();
        if (tid < NA) qs[tid] = qp[0][tid] + qp[1][tid];
        __syncthreads();
        // u[k][i] = sum_a Wk[k][i][a] * q[a]  : one i per warp iteration
        const int warp = tid >> 5, lane = tid & 31;
        for (int ii = 0; ii < NI / 8; ++ii) {
            const int i = warp * (NI / 8) + ii;
            const float* wk = Wk + ((size_t)(k * NI + i)) * NA;
            float p = wk[lane]      * qs[lane]
                    + wk[lane + 32] * qs[lane + 32]
                    + wk[lane + 64] * qs[lane + 64]
                    + wk[lane + 96] * qs[lane + 96];
            #pragma unroll
            for (int off = 16; off; off >>= 1) p += __shfl_xor_sync(0xffffffffu, p, off);
            if (lane == 0) g_u[k][i] = p;
        }
    } else {
        // hpre[k][h] for h-half hh, k = 0..2
        const int hh = bid - KACT;  // 0 or 1
        for (int j = tid; j < KACT * 128; j += 256) {
            const int k = j >> 7;
            const int h = hh * 128 + (j & 127);
            const float* rk = rim + k * NH;
            float acc = bias[h];
            #pragma unroll 8
            for (int hp = 0; hp < NH; ++hp) acc += rk[hp] * Whh[(size_t)hp * NH + h];
            g_hpre[k][h] = acc;
        }
    }
}

// ---------------------------------------------------------------------------
// Main: y[b][k][i] = sum_s x[b][s][i] * (x[b][s] . u[k]),  k = 0..2
// One warp streams 16 rows; float4 lane ownership of 4 columns.
// Deterministic reduction: warp regs -> smem (per-warp slots) -> global partials
// ---------------------------------------------------------------------------
__global__ __launch_bounds__(256) void main_kernel(const float* __restrict__ x)
{
    const int b     = blockIdx.x >> 4;      // /CHUNKS
    const int chunk = blockIdx.x & 15;
    const int warp  = threadIdx.x >> 5;
    const int lane  = threadIdx.x & 31;

    const size_t row0 = (size_t)b * NS + chunk * ROWS_PER_BLOCK + warp * ROWS_PER_WARP;
    const float4* xr = reinterpret_cast<const float4*>(x + row0 * NI) + lane;

    const float4 u0 = reinterpret_cast<const float4*>(g_u[0])[lane];
    const float4 u1 = reinterpret_cast<const float4*>(g_u[1])[lane];
    const float4 u2 = reinterpret_cast<const float4*>(g_u[2])[lane];

    float4 a0 = make_float4(0.f, 0.f, 0.f, 0.f);
    float4 a1 = a0, a2 = a0;

    #pragma unroll 4
    for (int r = 0; r < ROWS_PER_WARP; ++r) {
        const float4 xv = xr[r * 32];
        float d0 = xv.x * u0.x + xv.y * u0.y + xv.z * u0.z + xv.w * u0.w;
        float d1 = xv.x * u1.x + xv.y * u1.y + xv.z * u1.z + xv.w * u1.w;
        float d2 = xv.x * u2.x + xv.y * u2.y + xv.z * u2.z + xv.w * u2.w;
        #pragma unroll
        for (int off = 16; off; off >>= 1) {
            d0 += __shfl_xor_sync(0xffffffffu, d0, off);
            d1 += __shfl_xor_sync(0xffffffffu, d1, off);
            d2 += __shfl_xor_sync(0xffffffffu, d2, off);
        }
        a0.x += d0 * xv.x; a0.y += d0 * xv.y; a0.z += d0 * xv.z; a0.w += d0 * xv.w;
        a1.x += d1 * xv.x; a1.y += d1 * xv.y; a1.z += d1 * xv.z; a1.w += d1 * xv.w;
        a2.x += d2 * xv.x; a2.y += d2 * xv.y; a2.z += d2 * xv.z; a2.w += d2 * xv.w;
    }

    // per-warp staging: ysw[warp][k*128 + col], float4 stores (conflict-free)
    __shared__ float ysw[8][KACT * NI];
    reinterpret_cast<float4*>(&ysw[warp][0 * NI])[lane] = a0;
    reinterpret_cast<float4*>(&ysw[warp][1 * NI])[lane] = a1;
    reinterpret_cast<float4*>(&ysw[warp][2 * NI])[lane] = a2;
    __syncthreads();

    float* yp = g_ypart[b][chunk];
    for (int idx = threadIdx.x; idx < KACT * NI; idx += 256) {
        float s = 0.f;
        #pragma unroll
        for (int w = 0; w < 8; ++w) s += ysw[w][idx];
        yp[idx] = s;
    }
}

// ---------------------------------------------------------------------------
// Epilogue: per batch b —
//   y = sum over chunks;  att[k] = W_v[k]^T y[k];
//   out[b][k] = tanh(att[k] @ W_ih + hpre[k])  for k<3, else rim[k]
// ---------------------------------------------------------------------------
__global__ __launch_bounds__(256) void epilogue_kernel(
    const float* __restrict__ rim, const float* __restrict__ Wv,
    const float* __restrict__ Wih, float* __restrict__ out)
{
    const int b = blockIdx.x;
    const int tid = threadIdx.x;
    __shared__ float ys[KACT * NI];
    __shared__ float att[KACT * NA];

    // reduce partials (deterministic order)
    for (int idx = tid; idx < KACT * NI; idx += 256) {
        float s = 0.f;
        #pragma unroll
        for (int c = 0; c < CHUNKS; ++c) s += g_ypart[b][c][idx];
        ys[idx] = s;
    }
    __syncthreads();

    // attended[k][a] = sum_i Wv[k][i][a] * ys[k][i]
    for (int j = tid; j < KACT * NA; j += 256) {
        const int k = j >> 7, a = j & 127;
        const float* wv = Wv + (size_t)k * NI * NA + a;
        const float* yk = ys + k * NI;
        float acc = 0.f;
        #pragma unroll 8
        for (int i = 0; i < NI; ++i) acc += wv[(size_t)i * NA] * yk[i];
        att[j] = acc;
    }
    __syncthreads();

    float* ob = out + (size_t)b * NK * NH;

    // cand for k = 0..2
    for (int j = tid; j < KACT * NH; j += 256) {
        const int k = j >> 8, h = j & 255;
        const float* ak = att + k * NA;
        float acc = g_hpre[k][h];
        #pragma unroll 8
        for (int a = 0; a < NA; ++a) acc += ak[a] * Wih[(size_t)a * NH + h];
        ob[j] = tanhf(acc);
    }
    // k = 3..7: passthrough rim_hidden
    for (int j = tid; j < (NK - KACT) * NH; j += 256) {
        ob[KACT * NH + j] = rim[KACT * NH + j];
    }
}

// ---------------------------------------------------------------------------
extern "C" void kernel_launch(void* const* d_in, const int* in_sizes, int n_in,
                              void* d_out, int out_size)
{
    const float* x    = (const float*)d_in[0];
    const float* rim  = (const float*)d_in[1];
    const float* Wq   = (const float*)d_in[2];
    const float* Wk   = (const float*)d_in[3];
    const float* Wv   = (const float*)d_in[4];
    const float* Wih  = (const float*)d_in[5];
    const float* Whh  = (const float*)d_in[6];
    const float* bias = (const float*)d_in[7];
    float* out = (float*)d_out;

    prologue_kernel<<<KACT + 2, 256>>>(rim, Wq, Wk, Whh, bias);
    main_kernel<<<NB * CHUNKS, 256>>>(x);
    epilogue_kernel<<<NB, 256>>>(rim, Wv, Wih, out);
}

// round 2
// speedup vs baseline: 1.8206x; 1.8206x over previous
#include <cuda_runtime.h>
#include <cuda_bf16.h>

// Shapes: B=32, S=2048, I=128, A=128, H=256, K=8, ACTIVE=3 (structurally k=0,1,2)
#define NB 32
#define NS 2048
#define NI 128
#define NA 128
#define NH 256
#define NK 8
#define KACT 3
#define CHUNKS 16           // blocks per batch in main kernel
#define ROWS_PER_BLOCK (NS / CHUNKS)   // 128
#define ROWS_PER_WARP (ROWS_PER_BLOCK / 8) // 16

// Device scratch (allocation-free rule: __device__ globals)
__device__ float g_u[KACT][NI];                 // u[k] = W_k[k] @ q[k]
__device__ float g_hpre[KACT][NH];              // rim[k] @ W_hh + b
__device__ float g_ypart[NB][CHUNKS][KACT * NI]; // per-chunk partial y

// ---------------------------------------------------------------------------
// Prologue (latency-optimized):
//   blocks 0..2   : k = bid       -> q[k] then u[k]
//   blocks 3..14  : (k, h-quarter)-> hpre[k][h] with 4-way split reduction
// ---------------------------------------------------------------------------
__global__ __launch_bounds__(256) void prologue_kernel(
    const float* __restrict__ rim, const float* __restrict__ Wq,
    const float* __restrict__ Wk, const float* __restrict__ Whh,
    const float* __restrict__ bias)
{
    const int tid = threadIdx.x;
    const int bid = blockIdx.x;

    if (bid < KACT) {
        const int k = bid;
        __shared__ float qp[2][NA];
        __shared__ float qs[NA];

        // --- stage 1: q[k][a] = sum_h rim[k][h] * Wq[k][h][a]
        // thread: a = tid&127, h-half = tid>>7. 4 accumulators, deep unroll -> high MLP.
        {
            const int a  = tid & 127;
            const int hh = tid >> 7;       // 0 or 1
            const float* __restrict__ wq = Wq + ((size_t)(k * NH + hh * 128)) * NA + a;
            const float* __restrict__ rk = rim + k * NH + hh * 128;
            float acc0 = 0.f, acc1 = 0.f, acc2 = 0.f, acc3 = 0.f;
            #pragma unroll
            for (int h = 0; h < 128; h += 16) {
                acc0 += rk[h + 0]  * wq[(size_t)(h + 0)  * NA];
                acc1 += rk[h + 1]  * wq[(size_t)(h + 1)  * NA];
                acc2 += rk[h + 2]  * wq[(size_t)(h + 2)  * NA];
                acc3 += rk[h + 3]  * wq[(size_t)(h + 3)  * NA];
                acc0 += rk[h + 4]  * wq[(size_t)(h + 4)  * NA];
                acc1 += rk[h + 5]  * wq[(size_t)(h + 5)  * NA];
                acc2 += rk[h + 6]  * wq[(size_t)(h + 6)  * NA];
                acc3 += rk[h + 7]  * wq[(size_t)(h + 7)  * NA];
                acc0 += rk[h + 8]  * wq[(size_t)(h + 8)  * NA];
                acc1 += rk[h + 9]  * wq[(size_t)(h + 9)  * NA];
                acc2 += rk[h + 10] * wq[(size_t)(h + 10) * NA];
                acc3 += rk[h + 11] * wq[(size_t)(h + 11) * NA];
                acc0 += rk[h + 12] * wq[(size_t)(h + 12) * NA];
                acc1 += rk[h + 13] * wq[(size_t)(h + 13) * NA];
                acc2 += rk[h + 14] * wq[(size_t)(h + 14) * NA];
                acc3 += rk[h + 15] * wq[(size_t)(h + 15) * NA];
            }
            qp[hh][a] = (acc0 + acc1) + (acc2 + acc3);
        }
        __syncthreads();
        if (tid < NA) qs[tid] = qp[0][tid] + qp[1][tid];
        __syncthreads();

        // --- stage 2: u[k][i] = Wk[k][i][:] . q
        // One warp per 16 rows; one float4 per lane covers the whole 512B row.
        // Fully unrolled so independent shfl chains overlap the loads.
        const int warp = tid >> 5, lane = tid & 31;
        const float4 q4 = reinterpret_cast<const float4*>(qs)[lane];
        const float4* __restrict__ wkbase =
            reinterpret_cast<const float4*>(Wk + ((size_t)k * NI) * NA);
        #pragma unroll
        for (int ii = 0; ii < 16; ++ii) {
            const int i = warp * 16 + ii;
            const float4 w4 = wkbase[(size_t)i * 32 + lane];
            float p = w4.x * q4.x + w4.y * q4.y + w4.z * q4.z + w4.w * q4.w;
            #pragma unroll
            for (int off = 16; off; off >>= 1) p += __shfl_xor_sync(0xffffffffu, p, off);
            if (lane == 0) g_u[k][i] = p;
        }
    } else {
        // --- hpre[k][h] = bias[h] + sum_hp rim[k][hp] * Whh[hp][h]
        // block -> (k, quarter of h). thread: h = q*64 + (tid&63), part = tid>>6
        // splits the hp-reduction 4 ways (64 iters each), smem combine.
        const int idx = bid - KACT;
        const int k = idx >> 2;
        const int hq = idx & 3;
        const int h = hq * 64 + (tid & 63);
        const int part = tid >> 6;            // 0..3, hp range [part*64, part*64+64)
        const float* __restrict__ rk = rim + k * NH + part * 64;
        const float* __restrict__ wh = Whh + (size_t)(part * 64) * NH + h;

        float acc0 = 0.f, acc1 = 0.f, acc2 = 0.f, acc3 = 0.f;
        #pragma unroll
        for (int hp = 0; hp < 64; hp += 8) {
            acc0 += rk[hp + 0] * wh[(size_t)(hp + 0) * NH];
            acc1 += rk[hp + 1] * wh[(size_t)(hp + 1) * NH];
            acc2 += rk[hp + 2] * wh[(size_t)(hp + 2) * NH];
            acc3 += rk[hp + 3] * wh[(size_t)(hp + 3) * NH];
            acc0 += rk[hp + 4] * wh[(size_t)(hp + 4) * NH];
            acc1 += rk[hp + 5] * wh[(size_t)(hp + 5) * NH];
            acc2 += rk[hp + 6] * wh[(size_t)(hp + 6) * NH];
            acc3 += rk[hp + 7] * wh[(size_t)(hp + 7) * NH];
        }
        __shared__ float hp_s[4][64];
        hp_s[part][tid & 63] = (acc0 + acc1) + (acc2 + acc3);
        __syncthreads();
        if (tid < 64) {
            g_hpre[k][h] = bias[h] +
                ((hp_s[0][tid] + hp_s[1][tid]) + (hp_s[2][tid] + hp_s[3][tid]));
        }
    }
}

// ---------------------------------------------------------------------------
// Main: y[b][k][i] = sum_s x[b][s][i] * (x[b][s] . u[k]),  k = 0..2
// ---------------------------------------------------------------------------
__global__ __launch_bounds__(256) void main_kernel(const float* __restrict__ x)
{
    const int b     = blockIdx.x >> 4;      // /CHUNKS
    const int chunk = blockIdx.x & 15;
    const int warp  = threadIdx.x >> 5;
    const int lane  = threadIdx.x & 31;

    const size_t row0 = (size_t)b * NS + chunk * ROWS_PER_BLOCK + warp * ROWS_PER_WARP;
    const float4* xr = reinterpret_cast<const float4*>(x + row0 * NI) + lane;

    const float4 u0 = reinterpret_cast<const float4*>(g_u[0])[lane];
    const float4 u1 = reinterpret_cast<const float4*>(g_u[1])[lane];
    const float4 u2 = reinterpret_cast<const float4*>(g_u[2])[lane];

    float4 a0 = make_float4(0.f, 0.f, 0.f, 0.f);
    float4 a1 = a0, a2 = a0;

    #pragma unroll 4
    for (int r = 0; r < ROWS_PER_WARP; ++r) {
        const float4 xv = xr[r * 32];
        float d0 = xv.x * u0.x + xv.y * u0.y + xv.z * u0.z + xv.w * u0.w;
        float d1 = xv.x * u1.x + xv.y * u1.y + xv.z * u1.z + xv.w * u1.w;
        float d2 = xv.x * u2.x + xv.y * u2.y + xv.z * u2.z + xv.w * u2.w;
        #pragma unroll
        for (int off = 16; off; off >>= 1) {
            d0 += __shfl_xor_sync(0xffffffffu, d0, off);
            d1 += __shfl_xor_sync(0xffffffffu, d1, off);
            d2 += __shfl_xor_sync(0xffffffffu, d2, off);
        }
        a0.x += d0 * xv.x; a0.y += d0 * xv.y; a0.z += d0 * xv.z; a0.w += d0 * xv.w;
        a1.x += d1 * xv.x; a1.y += d1 * xv.y; a1.z += d1 * xv.z; a1.w += d1 * xv.w;
        a2.x += d2 * xv.x; a2.y += d2 * xv.y; a2.z += d2 * xv.z; a2.w += d2 * xv.w;
    }

    // per-warp staging: ysw[warp][k*128 + col], float4 stores (conflict-free)
    __shared__ float ysw[8][KACT * NI];
    reinterpret_cast<float4*>(&ysw[warp][0 * NI])[lane] = a0;
    reinterpret_cast<float4*>(&ysw[warp][1 * NI])[lane] = a1;
    reinterpret_cast<float4*>(&ysw[warp][2 * NI])[lane] = a2;
    __syncthreads();

    float* yp = g_ypart[b][chunk];
    for (int idx = threadIdx.x; idx < KACT * NI; idx += 256) {
        float s = 0.f;
        #pragma unroll
        for (int w = 0; w < 8; ++w) s += ysw[w][idx];
        yp[idx] = s;
    }
}

// ---------------------------------------------------------------------------
// Epilogue: per batch b —
//   y = sum over chunks;  att[k] = W_v[k]^T y[k];
//   out[b][k] = tanh(att[k] @ W_ih + hpre[k])  for k<3, else rim[k]
// ---------------------------------------------------------------------------
__global__ __launch_bounds__(256) void epilogue_kernel(
    const float* __restrict__ rim, const float* __restrict__ Wv,
    const float* __restrict__ Wih, float* __restrict__ out)
{
    const int b = blockIdx.x;
    const int tid = threadIdx.x;
    __shared__ float ys[KACT * NI];
    __shared__ float att[KACT * NA];

    // reduce partials (deterministic order)
    for (int idx = tid; idx < KACT * NI; idx += 256) {
        float s = 0.f;
        #pragma unroll
        for (int c = 0; c < CHUNKS; ++c) s += g_ypart[b][c][idx];
        ys[idx] = s;
    }
    __syncthreads();

    // attended[k][a] = sum_i Wv[k][i][a] * ys[k][i]
    for (int j = tid; j < KACT * NA; j += 256) {
        const int k = j >> 7, a = j & 127;
        const float* __restrict__ wv = Wv + (size_t)k * NI * NA + a;
        const float* __restrict__ yk = ys + k * NI;
        float acc0 = 0.f, acc1 = 0.f, acc2 = 0.f, acc3 = 0.f;
        #pragma unroll
        for (int i = 0; i < NI; i += 8) {
            acc0 += wv[(size_t)(i + 0) * NA] * yk[i + 0];
            acc1 += wv[(size_t)(i + 1) * NA] * yk[i + 1];
            acc2 += wv[(size_t)(i + 2) * NA] * yk[i + 2];
            acc3 += wv[(size_t)(i + 3) * NA] * yk[i + 3];
            acc0 += wv[(size_t)(i + 4) * NA] * yk[i + 4];
            acc1 += wv[(size_t)(i + 5) * NA] * yk[i + 5];
            acc2 += wv[(size_t)(i + 6) * NA] * yk[i + 6];
            acc3 += wv[(size_t)(i + 7) * NA] * yk[i + 7];
        }
        att[j] = (acc0 + acc1) + (acc2 + acc3);
    }
    __syncthreads();

    float* ob = out + (size_t)b * NK * NH;

    // cand for k = 0..2
    for (int j = tid; j < KACT * NH; j += 256) {
        const int k = j >> 8, h = j & 255;
        const float* __restrict__ ak = att + k * NA;
        float acc0 = g_hpre[k][h], acc1 = 0.f, acc2 = 0.f, acc3 = 0.f;
        #pragma unroll
        for (int a = 0; a < NA; a += 8) {
            acc0 += ak[a + 0] * Wih[(size_t)(a + 0) * NH + h];
            acc1 += ak[a + 1] * Wih[(size_t)(a + 1) * NH + h];
            acc2 += ak[a + 2] * Wih[(size_t)(a + 2) * NH + h];
            acc3 += ak[a + 3] * Wih[(size_t)(a + 3) * NH + h];
            acc0 += ak[a + 4] * Wih[(size_t)(a + 4) * NH + h];
            acc1 += ak[a + 5] * Wih[(size_t)(a + 5) * NH + h];
            acc2 += ak[a + 6] * Wih[(size_t)(a + 6) * NH + h];
            acc3 += ak[a + 7] * Wih[(size_t)(a + 7) * NH + h];
        }
        ob[j] = tanhf((acc0 + acc1) + (acc2 + acc3));
    }
    // k = 3..7: passthrough rim_hidden
    for (int j = tid; j < (NK - KACT) * NH; j += 256) {
        ob[KACT * NH + j] = rim[KACT * NH + j];
    }
}

// ---------------------------------------------------------------------------
extern "C" void kernel_launch(void* const* d_in, const int* in_sizes, int n_in,
                              void* d_out, int out_size)
{
    const float* x    = (const float*)d_in[0];
    const float* rim  = (const float*)d_in[1];
    const float* Wq   = (const float*)d_in[2];
    const float* Wk   = (const float*)d_in[3];
    const float* Wv   = (const float*)d_in[4];
    const float* Wih  = (const float*)d_in[5];
    const float* Whh  = (const float*)d_in[6];
    const float* bias = (const float*)d_in[7];
    float* out = (float*)d_out;

    prologue_kernel<<<KACT + 4 * KACT, 256>>>(rim, Wq, Wk, Whh, bias);
    main_kernel<<<NB * CHUNKS, 256>>>(x);
    epilogue_kernel<<<NB, 256>>>(rim, Wv, Wih, out);
}